// round 15
// baseline (speedup 1.0000x reference)
#include <cuda_runtime.h>
#include <cuda_fp16.h>
#include <math.h>

#define BATCHN 2
#define SEQ    2048
#define BLTOT  4096
#define DM     1024
#define DIN    2048
#define NH     32
#define HD     64
#define NK     32
#define CONVD  2176
#define DPROJ  4256
#define NCH    32
#define CH     64
#define LR     48
#define XBC_OFF 2048
#define DT_OFF  4224
#define T1_OFF  4256
#define ZXSTR   4352
#define THETA_CLIPF 1.5707963267948966f

#define NPAD_W 4352       // 34*128

typedef unsigned long long ull;

// ---------------- scratch (static device globals; no allocation) ----------------
__device__ __align__(256) float g_zx [BLTOT*ZXSTR];
__device__ __align__(256) float g_dt [BLTOT*NH];
__device__ __align__(256) float g_xs [BLTOT*DIN];
__device__ __align__(256) float g_Br [BLTOT*NK];
__device__ __align__(256) float g_Bi [BLTOT*NK];
__device__ __align__(256) float g_Cr [BLTOT*NK];
__device__ __align__(256) float g_Ci [BLTOT*NK];
__device__ __align__(256) float g_lzr[BLTOT*NH*NK];
__device__ __align__(256) float g_lzi[BLTOT*NH*NK];
__device__ __align__(256) float g_Pr [BATCHN*NCH*NH*CH*NK];
__device__ __align__(256) float g_Pi [BATCHN*NCH*NH*CH*NK];
__device__ __align__(256) float g_Er [BATCHN*NCH*NH*NK];
__device__ __align__(256) float g_Ei [BATCHN*NCH*NH*NK];
__device__ __align__(256) float g_Dr [BATCHN*NCH*NH*HD*NK];
__device__ __align__(256) float g_Di [BATCHN*NCH*NH*HD*NK];
__device__ __align__(256) float g_Sr [BATCHN*NCH*NH*HD*NK];
__device__ __align__(256) float g_Si [BATCHN*NCH*NH*HD*NK];
__device__ __align__(256) float g_y  [BLTOT*DIN];

// fp16 buffers (zero-initialized => pad rows are 0)
__device__ __align__(256) __half g_xh [BLTOT*DM];
__device__ __align__(256) __half g_wih[NPAD_W*DM];
__device__ __align__(256) __half g_gh [BLTOT*DIN];
__device__ __align__(256) __half g_woh[DM*DIN];

// ================= asm helpers ==================================================
#define LDSM4(R0,R1,R2,R3,ADDR) \
    asm volatile("ldmatrix.sync.aligned.m8n8.x4.shared.b16 {%0,%1,%2,%3}, [%4];" \
                 : "=r"(R0),"=r"(R1),"=r"(R2),"=r"(R3) : "r"(ADDR))

#define CP_ASYNC16(DST,SRC) \
    asm volatile("cp.async.cg.shared.global [%0], [%1], 16;" :: "r"(DST), "l"(SRC))
#define CP_COMMIT asm volatile("cp.async.commit_group;")
#define CP_WAITP  asm volatile("cp.async.wait_group 0;")

// packed f32x2 FMA: acc += a*b (elementwise)
#define FFMA2(ACC,A,B) \
    asm("fma.rn.f32x2 %0, %1, %2, %0;" : "+l"(ACC) : "l"(A), "l"(B))

__device__ __forceinline__ ull pack2(float x, float y)
{
    ull r; asm("mov.b64 %0, {%1, %2};" : "=l"(r) : "f"(x), "f"(y)); return r;
}
__device__ __forceinline__ float2 unpack2(ull v)
{
    float2 r; asm("mov.b64 {%0, %1}, %2;" : "=f"(r.x), "=f"(r.y) : "l"(v)); return r;
}

__device__ __forceinline__ unsigned smem_u32(const void* p)
{
    return (unsigned)__cvta_generic_to_shared(p);
}

__device__ __forceinline__ void mma_f16(float* d, const unsigned* a,
                                        unsigned b0, unsigned b1)
{
    asm volatile("mma.sync.aligned.m16n8k16.row.col.f32.f16.f16.f32 "
                 "{%0,%1,%2,%3}, {%4,%5,%6,%7}, {%8,%9}, {%0,%1,%2,%3};"
                 : "+f"(d[0]), "+f"(d[1]), "+f"(d[2]), "+f"(d[3])
                 : "r"(a[0]), "r"(a[1]), "r"(a[2]), "r"(a[3]), "r"(b0), "r"(b1));
}

// ================= fp16 GEMM: C[M,N] = A[M,K] * B[N,K]^T ========================
// 256x128 tile, 512 threads (16 warps: 8 M x 2 N), BK=64, 2-stage cp.async ring.
#define GSTR 72
#define NSTG 2
#define A_ROWS 256
#define B_ROWS 128
#define A_ELE (A_ROWS*GSTR)
#define B_ELE (B_ROWS*GSTR)
#define GEMM_SMEM (NSTG * (A_ELE + B_ELE) * 2)  // 110592 bytes

__global__ __launch_bounds__(512) void gemm_half(const __half* __restrict__ A,
                                                 const __half* __restrict__ B,
                                                 float* __restrict__ C,
                                                 int M, int N, int K)
{
    extern __shared__ __align__(16) __half smg[];
    __half* sA = smg;                      // [NSTG][256*GSTR]
    __half* sB = smg + NSTG*A_ELE;         // [NSTG][128*GSTR]

    int tid = threadIdx.x, lane = tid & 31, wid = tid >> 5;
    int wm = wid & 7;          // m offset = 32*wm  (0..7)
    int wn = wid >> 3;         // n offset = 64*wn  (0..1)
    int row0 = blockIdx.y * 256, col0 = blockIdx.x * 128;

    float acc[2][8][4];
    #pragma unroll
    for (int a = 0; a < 2; a++)
        #pragma unroll
        for (int b = 0; b < 8; b++)
            #pragma unroll
            for (int c = 0; c < 4; c++) acc[a][b][c] = 0.f;

    int NT = K >> 6;

    // prologue: stage 0
    {
        #pragma unroll
        for (int i = 0; i < 4; i++) {            // A: 256 rows
            int f = tid + i*512, r = f >> 3, kc = (f & 7) << 3;
            CP_ASYNC16(smem_u32(&sA[r*GSTR + kc]), A + (size_t)(row0+r)*K + kc);
        }
        #pragma unroll
        for (int i = 0; i < 2; i++) {            // B: 128 rows
            int f = tid + i*512, r = f >> 3, kc = (f & 7) << 3;
            CP_ASYNC16(smem_u32(&sB[r*GSTR + kc]), B + (size_t)(col0+r)*K + kc);
        }
        CP_COMMIT;
    }

    for (int kt = 0; kt < NT; kt++) {
        CP_WAITP;
        __syncthreads();

        {
            int kf = kt + 1;
            if (kf < NT) {
                int s = kf & 1, k0 = kf << 6;
                #pragma unroll
                for (int i = 0; i < 4; i++) {
                    int f = tid + i*512, r = f >> 3, kc = (f & 7) << 3;
                    CP_ASYNC16(smem_u32(&sA[s*A_ELE + r*GSTR + kc]), A + (size_t)(row0+r)*K + k0 + kc);
                }
                #pragma unroll
                for (int i = 0; i < 2; i++) {
                    int f = tid + i*512, r = f >> 3, kc = (f & 7) << 3;
                    CP_ASYNC16(smem_u32(&sB[s*B_ELE + r*GSTR + kc]), B + (size_t)(col0+r)*K + k0 + kc);
                }
                CP_COMMIT;
            }
        }

        const __half* a_s = sA + (kt & 1)*A_ELE;
        const __half* b_s = sB + (kt & 1)*B_ELE;

        #pragma unroll
        for (int kh = 0; kh < 64; kh += 16) {
            unsigned ah[2][4];
            #pragma unroll
            for (int mf = 0; mf < 2; mf++) {
                int r = wm*32 + mf*16 + (lane & 15);
                int cc = kh + ((lane >> 4) << 3);
                LDSM4(ah[mf][0], ah[mf][1], ah[mf][2], ah[mf][3],
                      smem_u32(&a_s[r*GSTR + cc]));
            }
            #pragma unroll
            for (int np = 0; np < 4; np++) {
                int nr  = wn*64 + np*16 + (lane & 7) + ((lane >> 4) << 3);
                int kof = kh + (((lane >> 3) & 1) << 3);
                unsigned bh[4];
                LDSM4(bh[0], bh[1], bh[2], bh[3], smem_u32(&b_s[nr*GSTR + kof]));
                #pragma unroll
                for (int mf = 0; mf < 2; mf++) {
                    mma_f16(acc[mf][np*2+0], ah[mf], bh[0], bh[1]);
                    mma_f16(acc[mf][np*2+1], ah[mf], bh[2], bh[3]);
                }
            }
        }
    }

    #pragma unroll
    for (int mf = 0; mf < 2; mf++) {
        int r = row0 + wm*32 + mf*16 + (lane >> 2);
        #pragma unroll
        for (int nf = 0; nf < 8; nf++) {
            int c = col0 + wn*64 + nf*8 + ((lane & 3) << 1);
            if (c + 1 < N) {
                *(float2*)&C[(size_t)r*N + c]     = make_float2(acc[mf][nf][0], acc[mf][nf][1]);
                *(float2*)&C[(size_t)(r+8)*N + c] = make_float2(acc[mf][nf][2], acc[mf][nf][3]);
            } else if (c < N) {
                C[(size_t)r*N + c]     = acc[mf][nf][0];
                C[(size_t)(r+8)*N + c] = acc[mf][nf][2];
            }
        }
    }
}

// ---------------- plain fp32 -> fp16 convert ------------------------------------
__global__ void tofp16_kernel(const float* __restrict__ src,
                              __half* __restrict__ dst, int n4)
{
    int i = blockIdx.x * blockDim.x + threadIdx.x;
    if (i >= n4) return;
    float4 v = *(const float4*)(src + i*4);
    __half2 a, b;
    a.x = __float2half(v.x); a.y = __float2half(v.y);
    b.x = __float2half(v.z); b.y = __float2half(v.w);
    ((__half2*)(dst + i*4))[0] = a;
    ((__half2*)(dst + i*4))[1] = b;
}

// ---------------- w1 (DM x LR) -> rows T1_OFF.. of g_wih ------------------------
__global__ void splitW1_kernel(const float* __restrict__ w1)
{
    int idx = blockIdx.x * blockDim.x + threadIdx.x;
    if (idx >= DM * LR) return;
    int k = idx / LR, n = idx % LR;
    g_wih[(size_t)(T1_OFF + n) * DM + k] = __float2half(w1[idx]);
}

// ---------------- dt = softplus(zx[:, DT_OFF+h] + dt_bias[h]) --------------------
__global__ void dt_kernel(const float* __restrict__ dt_bias)
{
    int idx = blockIdx.x * blockDim.x + threadIdx.x;
    if (idx >= BLTOT * NH) return;
    int bl = idx >> 5, hh = idx & 31;
    float v = g_zx[(size_t)bl * ZXSTR + DT_OFF + hh] + dt_bias[hh];
    float sp = (v > 20.f) ? v : log1pf(expf(v));
    g_dt[idx] = sp;
}

// ---------------- depthwise causal conv (smem-tiled) + silu + split --------------
__global__ __launch_bounds__(256) void conv_kernel(const float* __restrict__ conv_w,
                                                   const float* __restrict__ conv_b)
{
    __shared__ float tile[11][256];
    int tid = threadIdx.x;
    int c0 = blockIdx.x * 256;
    int bl0 = blockIdx.y * 8;
    int lblk = bl0 & (SEQ - 1);

    int c = c0 + tid;
    #pragma unroll
    for (int r = 0; r < 11; r++) {
        float v = 0.f;
        int off = r - 3;
        if (c < CONVD && lblk + off >= 0)
            v = g_zx[(size_t)(bl0 + off) * ZXSTR + XBC_OFF + c];
        tile[r][tid] = v;
    }
    __syncthreads();

    if (c >= CONVD) return;
    float w0 = conv_w[c*4+0], w1 = conv_w[c*4+1], w2 = conv_w[c*4+2], w3 = conv_w[c*4+3];
    float bias = conv_b[c];

    #pragma unroll
    for (int r = 0; r < 8; r++) {
        float acc = bias + tile[r][tid]*w0 + tile[r+1][tid]*w1
                         + tile[r+2][tid]*w2 + tile[r+3][tid]*w3;
        float a = acc / (1.f + __expf(-acc));
        int bl = bl0 + r;
        if (c < DIN) {
            g_xs[(size_t)bl * DIN + c] = a;
        } else {
            int c2 = c - DIN;
            if (c2 < 64) {
                int k = c2 >> 1;
                if (c2 & 1) g_Bi[bl*NK + k] = a; else g_Br[bl*NK + k] = a;
            } else {
                int c3 = c2 - 64;
                int k = c3 >> 1;
                if (c3 & 1) g_Ci[bl*NK + k] = a; else g_Cr[bl*NK + k] = a;
            }
        }
    }
}

// ---------------- lora2 (tanh applied on load, t1 from zx columns) ---------------
__global__ __launch_bounds__(256) void lora2_kernel(const float* __restrict__ w2,
                                                    const float* __restrict__ theta_base,
                                                    const float* __restrict__ lambda_base,
                                                    const float* __restrict__ eta)
{
    __shared__ float t1s[64][LR];
    __shared__ float w2s[LR][256];
    int tid = threadIdx.x;
    int row0 = blockIdx.y * 64;
    int col0 = blockIdx.x * 256;
    int n = col0 + tid;

    for (int idx = tid; idx < 64*LR; idx += 256) {
        int r = idx / LR, j = idx % LR;
        t1s[r][j] = tanhf(g_zx[(size_t)(row0 + r)*ZXSTR + T1_OFF + j]);
    }
    for (int idx = tid; idx < LR*256; idx += 256) {
        int j = idx >> 8, cc = idx & 255;
        w2s[j][cc] = w2[(size_t)j*(NH*NK) + col0 + cc];
    }
    __syncthreads();

    float tb = theta_base[n];
    float lb = lambda_base[n];
    float et = eta[n];
    int hh = n >> 5;

    for (int r = 0; r < 64; r++) {
        float acc = 0.f;
        #pragma unroll
        for (int j = 0; j < LR; j++) acc += t1s[r][j] * w2s[j][tid];
        float th = tb + acc;
        th = fminf(fmaxf(th, -THETA_CLIPF), THETA_CLIPF);
        float lam = lb + et * th * th;
        int bl = row0 + r;
        float dtv = g_dt[bl*NH + hh];
        g_lzr[(size_t)bl*(NH*NK) + n] = -lam * dtv;
        g_lzi[(size_t)bl*(NH*NK) + n] =  th * dtv;
    }
}

// ---------------- per-chunk kernel (factorized, transposed-v G loop) -------------
#define KS 34
#define O_CLR 0
#define O_CLI (1*64*KS)
#define O_CST (2*64*KS)
#define O_SNT (3*64*KS)
#define O_WRE (4*64*KS)
#define O_WIM (5*64*KS)
#define O_VR  (6*64*KS)
#define O_VI  (7*64*KS)
#define O_XD  (8*64*KS)            // 64x66
#define O_G   (8*64*KS + 64*66)    // 64x66
#define O_B63 (8*64*KS + 2*64*66)
#define CHUNK_FLOATS (O_B63 + 64)
#define CHUNK_SMEM (CHUNK_FLOATS*4)

__global__ __launch_bounds__(256) void chunk_kernel(const float* __restrict__ Dvec)
{
    extern __shared__ float sm[];
    float* clr = sm + O_CLR;
    float* cli = sm + O_CLI;
    float* csT = sm + O_CST;
    float* snT = sm + O_SNT;
    float* wre = sm + O_WRE;
    float* wim = sm + O_WIM;
    float* vr  = sm + O_VR;
    float* vi  = sm + O_VI;
    float* xd  = sm + O_XD;
    float* G   = sm + O_G;
    float* b63 = sm + O_B63;

    int tid = threadIdx.x;
    int bid = blockIdx.x;
    int h = bid & 31;
    int c = (bid >> 5) & 31;
    int b = bid >> 10;
    int blbase = b * SEQ + c * CH;

    for (int e = tid; e < CH*NK; e += 256) {
        int t = e >> 5, k = e & 31;
        int bl = blbase + t;
        clr[t*KS+k] = g_lzr[(size_t)bl*(NH*NK) + h*NK + k];
        cli[t*KS+k] = g_lzi[(size_t)bl*(NH*NK) + h*NK + k];
        wre[t*KS+k] = g_Cr[bl*NK + k];
        wim[t*KS+k] = g_Ci[bl*NK + k];
        vr [t*KS+k] = g_Br[bl*NK + k];
        vi [t*KS+k] = g_Bi[bl*NK + k];
    }
    for (int e = tid; e < CH*HD; e += 256) {
        int t = e >> 6, p = e & 63;
        int bl = blbase + t;
        xd[t*66+p] = g_xs[(size_t)bl*DIN + h*HD + p] * g_dt[bl*NH + h];
    }
    __syncthreads();

    if (tid < 32) {
        float sr = 0.f, si = 0.f;
        for (int t = 0; t < CH; t++) {
            sr += clr[t*KS+tid]; si += cli[t*KS+tid];
            clr[t*KS+tid] = sr;  cli[t*KS+tid] = si;
        }
    }
    __syncthreads();

    for (int e = tid; e < CH*NK; e += 256) {
        int t = e >> 5, k = e & 31;
        float cs, sn; __sincosf(cli[t*KS+k], &sn, &cs);
        csT[t*KS+k] = cs; snT[t*KS+k] = sn;
        float er = __expf(clr[t*KS+k]);
        float exr = er*cs, exi = er*sn;
        float cr = wre[t*KS+k], ci = wim[t*KS+k];
        size_t base = (size_t)bid*(CH*NK) + t*NK + k;
        g_Pr[base] = cr*exr - ci*exi;
        g_Pi[base] = cr*exi + ci*exr;
        float br = vr[t*KS+k], bi = vi[t*KS+k];
        if (t == CH-1) {
            g_Er[bid*NK + k] = exr; g_Ei[bid*NK + k] = exi;
            b63[k] = br; b63[32+k] = bi;
        }
        float cbr = cr*br - ci*bi;
        float cbi = cr*bi + ci*br;
        int bs = t & ~15;
        float refI = (bs > 0) ? clr[(bs-1)*KS+k] : 0.f;
        float eu = __expf(clr[t*KS+k] - refI);
        float Ur = eu*cs, Ui = eu*sn;
        wre[t*KS+k] =  cbr*Ur - cbi*Ui;
        wim[t*KS+k] = -(cbr*Ui + cbi*Ur);
    }
    __syncthreads();

    int sp = tid & 31, tg = tid >> 5;
    for (int I = 0; I < 4; I++) {
        int tI0 = I << 4;
        for (int e = tid; e < NK*CH; e += 256) {
            int k = e >> 6, s = e & 63;
            float vre = 0.f, vim_ = 0.f;
            if (s < tI0 + 16) {
                float refI = (I > 0) ? clr[(tI0-1)*KS+k] : 0.f;
                float ev = __expf(refI - clr[s*KS+k]);
                vre  =  ev * csT[s*KS+k];
                vim_ = -ev * snT[s*KS+k];
            }
            vr[k*66+s] = vre;
            vi[k*66+s] = vim_;
        }
        __syncthreads();

        {
            int tA = tI0 + tg, tB = tA + 8;
            int s2 = sp << 1;
            ull accA = 0ULL, accB = 0ULL;
            #pragma unroll 4
            for (int k = 0; k < NK; k++) {
                ull v_r = *(const ull*)&vr[k*66 + s2];
                ull v_i = *(const ull*)&vi[k*66 + s2];
                float wrA = wre[tA*KS+k], wiA = wim[tA*KS+k];
                float wrB = wre[tB*KS+k], wiB = wim[tB*KS+k];
                FFMA2(accA, pack2(wrA, wrA), v_r);
                FFMA2(accA, pack2(wiA, wiA), v_i);
                FFMA2(accB, pack2(wrB, wrB), v_r);
                FFMA2(accB, pack2(wiB, wiB), v_i);
            }
            float2 aA = unpack2(accA), aB = unpack2(accB);
            float2 gA = make_float2((s2   <= tA) ? aA.x : 0.f,
                                    (s2+1 <= tA) ? aA.y : 0.f);
            float2 gB = make_float2((s2   <= tB) ? aB.x : 0.f,
                                    (s2+1 <= tB) ? aB.y : 0.f);
            *(float2*)&G[tA*66 + s2] = gA;
            *(float2*)&G[tB*66 + s2] = gB;
        }
        __syncthreads();
    }

    float Dh = Dvec[h];
    for (int e = tid; e < CH*16; e += 256) {
        int t = e >> 4, pq = (e & 15) << 2;
        ull a0 = 0ULL, a1 = 0ULL;
        for (int s = 0; s <= t; s++) {
            float gv = G[t*66+s];
            ull g2 = pack2(gv, gv);
            ull x0 = *(const ull*)&xd[s*66+pq];
            ull x1 = *(const ull*)&xd[s*66+pq+2];
            FFMA2(a0, g2, x0);
            FFMA2(a1, g2, x1);
        }
        float2 r0 = unpack2(a0), r1 = unpack2(a1);
        size_t yi = (size_t)(blbase + t)*DIN + h*HD + pq;
        float4 xv = *(const float4*)&g_xs[yi];
        float4 out4 = make_float4(r0.x + Dh*xv.x, r0.y + Dh*xv.y,
                                  r1.x + Dh*xv.z, r1.y + Dh*xv.w);
        *(float4*)&g_y[yi] = out4;
    }
    __syncthreads();

    for (int e = tid; e < CH*NK; e += 256) {
        int s = e >> 5, k = e & 31;
        float er = __expf(clr[(CH-1)*KS+k] - clr[s*KS+k]);
        float c63 = csT[(CH-1)*KS+k], s63 = snT[(CH-1)*KS+k];
        float css = csT[s*KS+k],      sns = snT[s*KS+k];
        vr[s*KS+k] = er * (c63*css + s63*sns);
        vi[s*KS+k] = er * (s63*css - c63*sns);
    }
    __syncthreads();

    for (int e = tid; e < HD*16; e += 256) {
        int p = e >> 4, k = (e & 15) << 1;
        ull ar = 0ULL, ai = 0ULL;
        for (int s = 0; s < CH; s++) {
            float xv = xd[s*66+p];
            ull x2 = pack2(xv, xv);
            ull v_r = *(const ull*)&vr[s*KS+k];
            ull v_i = *(const ull*)&vi[s*KS+k];
            FFMA2(ar, x2, v_r);
            FFMA2(ai, x2, v_i);
        }
        float2 arf = unpack2(ar), aif = unpack2(ai);
        float br0 = b63[k],   bi0 = b63[32+k];
        float br1 = b63[k+1], bi1 = b63[32+k+1];
        size_t di_ = (size_t)bid*(HD*NK) + p*NK + k;
        g_Dr[di_]   = br0*arf.x - bi0*aif.x;
        g_Di[di_]   = br0*aif.x + bi0*arf.x;
        g_Dr[di_+1] = br1*arf.y - bi1*aif.y;
        g_Di[di_+1] = br1*aif.y + bi1*arf.y;
    }
}

// ---------------- sequential scan over chunks (per b,h,p,k) ----------------------
__global__ void scan_kernel()
{
    int idx = blockIdx.x * blockDim.x + threadIdx.x;
    int k = idx & 31;
    int p = (idx >> 5) & 63;
    int h = (idx >> 11) & 31;
    int b = idx >> 16;
    float sr = 0.f, si = 0.f;
    for (int c = 0; c < NCH; c++) {
        int bidl = (b*NCH + c)*NH + h;
        size_t di_ = (size_t)bidl*(HD*NK) + p*NK + k;
        g_Sr[di_] = sr; g_Si[di_] = si;
        float er = g_Er[bidl*NK + k], ei = g_Ei[bidl*NK + k];
        float dr = g_Dr[di_], dimg = g_Di[di_];
        float nr = er*sr - ei*si + dr;
        float ni = er*si + ei*sr + dimg;
        sr = nr; si = ni;
    }
}

// ---------------- y += Re( P[t,k] * S_entry[p,k] )  (transposed S, packed) -------
__global__ __launch_bounds__(256) void yinter_kernel()
{
    __shared__ float Pr[CH*KS], Pi[CH*KS];
    __shared__ float SrT[NK*66], SiT[NK*66];
    int tid = threadIdx.x, bid = blockIdx.x;
    int h = bid & 31, c = (bid >> 5) & 31, b = bid >> 10;
    size_t base = (size_t)bid * (CH*NK);
    for (int e = tid; e < CH*NK; e += 256) {
        int t = e >> 5, k = e & 31;
        Pr[t*KS+k] =  g_Pr[base + e];
        Pi[t*KS+k] = -g_Pi[base + e];
        SrT[k*66+t] = g_Sr[base + e];
        SiT[k*66+t] = g_Si[base + e];
    }
    __syncthreads();
    int blbase = b*SEQ + c*CH;
    int sp = tid & 31, tg = tid >> 5;
    int p2 = sp << 1;
    #pragma unroll
    for (int it = 0; it < 4; it++) {
        int tA = 2*tg + 16*it, tB = tA + 1;
        ull aA = 0ULL, aB = 0ULL;
        #pragma unroll 4
        for (int k = 0; k < NK; k++) {
            ull s_r = *(const ull*)&SrT[k*66 + p2];
            ull s_i = *(const ull*)&SiT[k*66 + p2];
            float prA = Pr[tA*KS+k], piA = Pi[tA*KS+k];
            float prB = Pr[tB*KS+k], piB = Pi[tB*KS+k];
            FFMA2(aA, pack2(prA, prA), s_r);
            FFMA2(aA, pack2(piA, piA), s_i);
            FFMA2(aB, pack2(prB, prB), s_r);
            FFMA2(aB, pack2(piB, piB), s_i);
        }
        float2 fA = unpack2(aA), fB = unpack2(aB);
        size_t yA = (size_t)(blbase + tA)*DIN + h*HD + p2;
        size_t yB = (size_t)(blbase + tB)*DIN + h*HD + p2;
        float2 yvA = *(float2*)&g_y[yA];
        float2 yvB = *(float2*)&g_y[yB];
        yvA.x += fA.x; yvA.y += fA.y;
        yvB.x += fB.x; yvB.y += fB.y;
        *(float2*)&g_y[yA] = yvA;
        *(float2*)&g_y[yB] = yvB;
    }
}

// ---------------- gating + RMSNorm -> fp16 ---------------------------------------
__global__ __launch_bounds__(256) void gatenorm_kernel(const float* __restrict__ norm_w)
{
    __shared__ float red[8];
    int bl = blockIdx.x, tid = threadIdx.x;
    float gv[8];
    float local = 0.f;
    #pragma unroll
    for (int i = 0; i < 8; i++) {
        int j = tid + i*256;
        float z = g_zx[(size_t)bl*ZXSTR + j];
        float y = g_y[(size_t)bl*DIN + j];
        float sig = 1.f / (1.f + __expf(-z));
        float g = y * z * sig;
        gv[i] = g;
        local += g * g;
    }
    #pragma unroll
    for (int o = 16; o; o >>= 1) local += __shfl_xor_sync(0xffffffffu, local, o);
    if ((tid & 31) == 0) red[tid >> 5] = local;
    __syncthreads();
    if (tid == 0) {
        float s = 0.f;
        for (int i = 0; i < 8; i++) s += red[i];
        red[0] = rsqrtf(s / (float)DIN + 1e-5f);
    }
    __syncthreads();
    float sc = red[0];
    size_t ro = (size_t)bl * DIN;
    #pragma unroll
    for (int i = 0; i < 8; i++) {
        int j = tid + i*256;
        g_gh[ro + j] = __float2half(gv[i] * sc * norm_w[j]);
    }
}

// ---------------- launch ---------------------------------------------------------
extern "C" void kernel_launch(void* const* d_in, const int* in_sizes, int n_in,
                              void* d_out, int out_size)
{
    (void)in_sizes; (void)n_in; (void)out_size;
    const float* x       = (const float*)d_in[0];
    const float* in_w    = (const float*)d_in[1];
    const float* conv_w  = (const float*)d_in[2];
    const float* conv_b  = (const float*)d_in[3];
    const float* dt_bias = (const float*)d_in[4];
    const float* lam_b   = (const float*)d_in[5];
    const float* th_b    = (const float*)d_in[6];
    const float* w1      = (const float*)d_in[7];
    const float* w2      = (const float*)d_in[8];
    const float* eta     = (const float*)d_in[9];
    const float* Dv      = (const float*)d_in[10];
    const float* nw      = (const float*)d_in[11];
    const float* out_w   = (const float*)d_in[12];
    float* out = (float*)d_out;

    float *zx = nullptr;
    __half *xh, *wih, *gh, *woh;
    cudaGetSymbolAddress((void**)&zx,  g_zx);
    cudaGetSymbolAddress((void**)&xh,  g_xh);
    cudaGetSymbolAddress((void**)&wih, g_wih);
    cudaGetSymbolAddress((void**)&gh,  g_gh);
    cudaGetSymbolAddress((void**)&woh, g_woh);

    cudaFuncSetAttribute(gemm_half, cudaFuncAttributeMaxDynamicSharedMemorySize, GEMM_SMEM);
    cudaFuncSetAttribute(chunk_kernel, cudaFuncAttributeMaxDynamicSharedMemorySize, CHUNK_SMEM);

    // 0) converts
    tofp16_kernel<<<(BLTOT*DM/4+255)/256, 256>>>(x, xh, BLTOT*DM/4);
    tofp16_kernel<<<(DPROJ*DM/4+255)/256, 256>>>(in_w, wih, DPROJ*DM/4);
    splitW1_kernel<<<(DM*LR+255)/256, 256>>>(w1);
    tofp16_kernel<<<(DM*DIN/4+255)/256, 256>>>(out_w, woh, DM*DIN/4);

    // 1) in_proj (+fused lora1): 256x128 tiles
    gemm_half<<<dim3(NPAD_W/128, BLTOT/256), 512, GEMM_SMEM>>>(xh, wih, zx, BLTOT, ZXSTR, DM);
    // 2) dt
    dt_kernel<<<(BLTOT*NH + 255)/256, 256>>>(dt_bias);
    // 3) conv (tiled) + silu + split
    conv_kernel<<<dim3(9, BLTOT/8), 256>>>(conv_w, conv_b);
    // 4) lora stage 2 + log_z
    lora2_kernel<<<dim3(4, BLTOT/64), 256>>>(w2, th_b, lam_b, eta);
    // 5) chunk-parallel heavy kernel
    chunk_kernel<<<BATCHN*NCH*NH, 256, CHUNK_SMEM>>>(Dv);
    // 6) inter-chunk state scan
    scan_kernel<<<(BATCHN*NH*HD*NK)/256, 256>>>();
    // 7) y += P * S_entry
    yinter_kernel<<<BATCHN*NCH*NH, 256>>>();
    // 8) gate + rmsnorm -> fp16
    gatenorm_kernel<<<BLTOT, 256>>>(nw);
    // 9) out_proj: 256x128 tiles
    gemm_half<<<dim3(DM/128, BLTOT/256), 512, GEMM_SMEM>>>(gh, woh, out, BLTOT, DM, DIN);
}

// round 16
// speedup vs baseline: 1.0454x; 1.0454x over previous
#include <cuda_runtime.h>
#include <cuda_fp16.h>
#include <math.h>

#define BATCHN 2
#define SEQ    2048
#define BLTOT  4096
#define DM     1024
#define DIN    2048
#define NH     32
#define HD     64
#define NK     32
#define CONVD  2176
#define DPROJ  4256
#define NCH    32
#define CH     64
#define LR     48
#define XBC_OFF 2048
#define DT_OFF  4224
#define T1_OFF  4256
#define ZXSTR   4352
#define THETA_CLIPF 1.5707963267948966f

#define NPAD_W 4352       // 34*128

typedef unsigned long long ull;

// ---------------- scratch (static device globals; no allocation) ----------------
__device__ __align__(256) float g_zx [BLTOT*ZXSTR];
__device__ __align__(256) float g_dt [BLTOT*NH];
__device__ __align__(256) float g_xs [BLTOT*DIN];
__device__ __align__(256) float g_Br [BLTOT*NK];
__device__ __align__(256) float g_Bi [BLTOT*NK];
__device__ __align__(256) float g_Cr [BLTOT*NK];
__device__ __align__(256) float g_Ci [BLTOT*NK];
__device__ __align__(256) float g_lzr[BLTOT*NH*NK];
__device__ __align__(256) float g_lzi[BLTOT*NH*NK];
__device__ __align__(256) float g_Pr [BATCHN*NCH*NH*CH*NK];
__device__ __align__(256) float g_Pi [BATCHN*NCH*NH*CH*NK];
__device__ __align__(256) float g_Er [BATCHN*NCH*NH*NK];
__device__ __align__(256) float g_Ei [BATCHN*NCH*NH*NK];
__device__ __align__(256) float g_Dr [BATCHN*NCH*NH*HD*NK];
__device__ __align__(256) float g_Di [BATCHN*NCH*NH*HD*NK];
__device__ __align__(256) float g_Sr [BATCHN*NCH*NH*HD*NK];
__device__ __align__(256) float g_Si [BATCHN*NCH*NH*HD*NK];
__device__ __align__(256) float g_y  [BLTOT*DIN];

// fp16 buffers (zero-initialized => pad rows are 0)
__device__ __align__(256) __half g_xh [BLTOT*DM];
__device__ __align__(256) __half g_wih[NPAD_W*DM];
__device__ __align__(256) __half g_gh [BLTOT*DIN];
__device__ __align__(256) __half g_woh[DM*DIN];

// ================= asm helpers ==================================================
#define LDSM4(R0,R1,R2,R3,ADDR) \
    asm volatile("ldmatrix.sync.aligned.m8n8.x4.shared.b16 {%0,%1,%2,%3}, [%4];" \
                 : "=r"(R0),"=r"(R1),"=r"(R2),"=r"(R3) : "r"(ADDR))

#define CP_ASYNC16(DST,SRC) \
    asm volatile("cp.async.cg.shared.global [%0], [%1], 16;" :: "r"(DST), "l"(SRC))
#define CP_COMMIT asm volatile("cp.async.commit_group;")
#define CP_WAITP  asm volatile("cp.async.wait_group 0;")

// packed f32x2 FMA: acc += a*b (elementwise)
#define FFMA2(ACC,A,B) \
    asm("fma.rn.f32x2 %0, %1, %2, %0;" : "+l"(ACC) : "l"(A), "l"(B))

__device__ __forceinline__ ull pack2(float x, float y)
{
    ull r; asm("mov.b64 %0, {%1, %2};" : "=l"(r) : "f"(x), "f"(y)); return r;
}
__device__ __forceinline__ float2 unpack2(ull v)
{
    float2 r; asm("mov.b64 {%0, %1}, %2;" : "=f"(r.x), "=f"(r.y) : "l"(v)); return r;
}

__device__ __forceinline__ unsigned smem_u32(const void* p)
{
    return (unsigned)__cvta_generic_to_shared(p);
}

__device__ __forceinline__ void mma_f16(float* d, const unsigned* a,
                                        unsigned b0, unsigned b1)
{
    asm volatile("mma.sync.aligned.m16n8k16.row.col.f32.f16.f16.f32 "
                 "{%0,%1,%2,%3}, {%4,%5,%6,%7}, {%8,%9}, {%0,%1,%2,%3};"
                 : "+f"(d[0]), "+f"(d[1]), "+f"(d[2]), "+f"(d[3])
                 : "r"(a[0]), "r"(a[1]), "r"(a[2]), "r"(a[3]), "r"(b0), "r"(b1));
}

// ================= fp16 GEMM: C[M,N] = A[M,K] * B[N,K]^T ========================
// 128x128 tile, BK=64, 2-stage cp.async double buffer, 2 CTAs/SM.  (R12 config)
#define GSTR 72
#define NSTG 2
#define STG_ELE (128*GSTR)
#define GEMM_SMEM (NSTG * 2 * STG_ELE * 2)  // 73728 bytes

__global__ __launch_bounds__(256, 2) void gemm_half(const __half* __restrict__ A,
                                                    const __half* __restrict__ B,
                                                    float* __restrict__ C,
                                                    int M, int N, int K)
{
    extern __shared__ __align__(16) __half smg[];
    __half* sA = smg;
    __half* sB = smg + NSTG*STG_ELE;

    int tid = threadIdx.x, lane = tid & 31, wid = tid >> 5;
    int wm = wid & 3;
    int wn = wid >> 2;
    int row0 = blockIdx.y * 128, col0 = blockIdx.x * 128;

    float acc[2][8][4];
    #pragma unroll
    for (int a = 0; a < 2; a++)
        #pragma unroll
        for (int b = 0; b < 8; b++)
            #pragma unroll
            for (int c = 0; c < 4; c++) acc[a][b][c] = 0.f;

    int NT = K >> 6;

    {
        #pragma unroll
        for (int i = 0; i < 4; i++) {
            int f = tid + i*256, r = f >> 3, kc = (f & 7) << 3;
            CP_ASYNC16(smem_u32(&sA[r*GSTR + kc]), A + (size_t)(row0+r)*K + kc);
            CP_ASYNC16(smem_u32(&sB[r*GSTR + kc]), B + (size_t)(col0+r)*K + kc);
        }
        CP_COMMIT;
    }

    for (int kt = 0; kt < NT; kt++) {
        CP_WAITP;
        __syncthreads();

        {
            int kf = kt + 1;
            if (kf < NT) {
                int s = kf & 1, k0 = kf << 6;
                #pragma unroll
                for (int i = 0; i < 4; i++) {
                    int f = tid + i*256, r = f >> 3, kc = (f & 7) << 3;
                    CP_ASYNC16(smem_u32(&sA[s*STG_ELE + r*GSTR + kc]), A + (size_t)(row0+r)*K + k0 + kc);
                    CP_ASYNC16(smem_u32(&sB[s*STG_ELE + r*GSTR + kc]), B + (size_t)(col0+r)*K + k0 + kc);
                }
                CP_COMMIT;
            }
        }

        const __half* a_s = sA + (kt & 1)*STG_ELE;
        const __half* b_s = sB + (kt & 1)*STG_ELE;

        #pragma unroll
        for (int kh = 0; kh < 64; kh += 16) {
            unsigned ah[2][4];
            #pragma unroll
            for (int mf = 0; mf < 2; mf++) {
                int r = wm*32 + mf*16 + (lane & 15);
                int cc = kh + ((lane >> 4) << 3);
                LDSM4(ah[mf][0], ah[mf][1], ah[mf][2], ah[mf][3],
                      smem_u32(&a_s[r*GSTR + cc]));
            }
            #pragma unroll
            for (int np = 0; np < 4; np++) {
                int nr  = wn*64 + np*16 + (lane & 7) + ((lane >> 4) << 3);
                int kof = kh + (((lane >> 3) & 1) << 3);
                unsigned bh[4];
                LDSM4(bh[0], bh[1], bh[2], bh[3], smem_u32(&b_s[nr*GSTR + kof]));
                #pragma unroll
                for (int mf = 0; mf < 2; mf++) {
                    mma_f16(acc[mf][np*2+0], ah[mf], bh[0], bh[1]);
                    mma_f16(acc[mf][np*2+1], ah[mf], bh[2], bh[3]);
                }
            }
        }
    }

    #pragma unroll
    for (int mf = 0; mf < 2; mf++) {
        int r = row0 + wm*32 + mf*16 + (lane >> 2);
        #pragma unroll
        for (int nf = 0; nf < 8; nf++) {
            int c = col0 + wn*64 + nf*8 + ((lane & 3) << 1);
            if (c + 1 < N) {
                *(float2*)&C[(size_t)r*N + c]     = make_float2(acc[mf][nf][0], acc[mf][nf][1]);
                *(float2*)&C[(size_t)(r+8)*N + c] = make_float2(acc[mf][nf][2], acc[mf][nf][3]);
            } else if (c < N) {
                C[(size_t)r*N + c]     = acc[mf][nf][0];
                C[(size_t)(r+8)*N + c] = acc[mf][nf][2];
            }
        }
    }
}

// ---------------- plain fp32 -> fp16 convert ------------------------------------
__global__ void tofp16_kernel(const float* __restrict__ src,
                              __half* __restrict__ dst, int n4)
{
    int i = blockIdx.x * blockDim.x + threadIdx.x;
    if (i >= n4) return;
    float4 v = *(const float4*)(src + i*4);
    __half2 a, b;
    a.x = __float2half(v.x); a.y = __float2half(v.y);
    b.x = __float2half(v.z); b.y = __float2half(v.w);
    ((__half2*)(dst + i*4))[0] = a;
    ((__half2*)(dst + i*4))[1] = b;
}

// ---------------- w1 (DM x LR) -> rows T1_OFF.. of g_wih ------------------------
__global__ void splitW1_kernel(const float* __restrict__ w1)
{
    int idx = blockIdx.x * blockDim.x + threadIdx.x;
    if (idx >= DM * LR) return;
    int k = idx / LR, n = idx % LR;
    g_wih[(size_t)(T1_OFF + n) * DM + k] = __float2half(w1[idx]);
}

// ---------------- depthwise causal conv (smem-tiled) + silu + split + dt ---------
// channels [0, CONVD): conv.  channels [CONVD, CONVD+NH): dt = softplus(...).
// Note XBC_OFF + CONVD == DT_OFF, so the tile already holds the dt inputs.
__global__ __launch_bounds__(256) void conv_kernel(const float* __restrict__ conv_w,
                                                   const float* __restrict__ conv_b,
                                                   const float* __restrict__ dt_bias)
{
    __shared__ float tile[11][256];
    int tid = threadIdx.x;
    int c0 = blockIdx.x * 256;
    int bl0 = blockIdx.y * 8;
    int lblk = bl0 & (SEQ - 1);

    int c = c0 + tid;
    #pragma unroll
    for (int r = 0; r < 11; r++) {
        float v = 0.f;
        int off = r - 3;
        if (c < CONVD + NH && lblk + off >= 0)
            v = g_zx[(size_t)(bl0 + off) * ZXSTR + XBC_OFF + c];
        tile[r][tid] = v;
    }
    __syncthreads();

    if (c >= CONVD + NH) return;

    if (c >= CONVD) {
        int hh = c - CONVD;
        float bsv = dt_bias[hh];
        #pragma unroll
        for (int r = 0; r < 8; r++) {
            float v = tile[r+3][tid] + bsv;
            float sp = (v > 20.f) ? v : log1pf(expf(v));
            g_dt[(bl0 + r)*NH + hh] = sp;
        }
        return;
    }

    float w0 = conv_w[c*4+0], w1 = conv_w[c*4+1], w2 = conv_w[c*4+2], w3 = conv_w[c*4+3];
    float bias = conv_b[c];

    #pragma unroll
    for (int r = 0; r < 8; r++) {
        float acc = bias + tile[r][tid]*w0 + tile[r+1][tid]*w1
                         + tile[r+2][tid]*w2 + tile[r+3][tid]*w3;
        float a = acc / (1.f + __expf(-acc));
        int bl = bl0 + r;
        if (c < DIN) {
            g_xs[(size_t)bl * DIN + c] = a;
        } else {
            int c2 = c - DIN;
            if (c2 < 64) {
                int k = c2 >> 1;
                if (c2 & 1) g_Bi[bl*NK + k] = a; else g_Br[bl*NK + k] = a;
            } else {
                int c3 = c2 - 64;
                int k = c3 >> 1;
                if (c3 & 1) g_Ci[bl*NK + k] = a; else g_Cr[bl*NK + k] = a;
            }
        }
    }
}

// ---------------- lora2 (tanh applied on load, t1 from zx columns) ---------------
__global__ __launch_bounds__(256) void lora2_kernel(const float* __restrict__ w2,
                                                    const float* __restrict__ theta_base,
                                                    const float* __restrict__ lambda_base,
                                                    const float* __restrict__ eta)
{
    __shared__ float t1s[64][LR];
    __shared__ float w2s[LR][256];
    int tid = threadIdx.x;
    int row0 = blockIdx.y * 64;
    int col0 = blockIdx.x * 256;
    int n = col0 + tid;

    for (int idx = tid; idx < 64*LR; idx += 256) {
        int r = idx / LR, j = idx % LR;
        t1s[r][j] = tanhf(g_zx[(size_t)(row0 + r)*ZXSTR + T1_OFF + j]);
    }
    for (int idx = tid; idx < LR*256; idx += 256) {
        int j = idx >> 8, cc = idx & 255;
        w2s[j][cc] = w2[(size_t)j*(NH*NK) + col0 + cc];
    }
    __syncthreads();

    float tb = theta_base[n];
    float lb = lambda_base[n];
    float et = eta[n];
    int hh = n >> 5;

    for (int r = 0; r < 64; r++) {
        float acc = 0.f;
        #pragma unroll
        for (int j = 0; j < LR; j++) acc += t1s[r][j] * w2s[j][tid];
        float th = tb + acc;
        th = fminf(fmaxf(th, -THETA_CLIPF), THETA_CLIPF);
        float lam = lb + et * th * th;
        int bl = row0 + r;
        float dtv = g_dt[bl*NH + hh];
        g_lzr[(size_t)bl*(NH*NK) + n] = -lam * dtv;
        g_lzi[(size_t)bl*(NH*NK) + n] =  th * dtv;
    }
}

// ---------------- per-chunk kernel (factorized, 512 threads) ---------------------
#define KS 34
#define O_CLR 0
#define O_CLI (1*64*KS)
#define O_CST (2*64*KS)
#define O_SNT (3*64*KS)
#define O_WRE (4*64*KS)
#define O_WIM (5*64*KS)
#define O_VR  (6*64*KS)
#define O_VI  (7*64*KS)
#define O_XD  (8*64*KS)            // 64x66
#define O_G   (8*64*KS + 64*66)    // 64x66
#define O_B63 (8*64*KS + 2*64*66)
#define CHUNK_FLOATS (O_B63 + 64)
#define CHUNK_SMEM (CHUNK_FLOATS*4)
#define CTH 512

__global__ __launch_bounds__(CTH) void chunk_kernel(const float* __restrict__ Dvec)
{
    extern __shared__ float sm[];
    float* clr = sm + O_CLR;
    float* cli = sm + O_CLI;
    float* csT = sm + O_CST;
    float* snT = sm + O_SNT;
    float* wre = sm + O_WRE;
    float* wim = sm + O_WIM;
    float* vr  = sm + O_VR;
    float* vi  = sm + O_VI;
    float* xd  = sm + O_XD;
    float* G   = sm + O_G;
    float* b63 = sm + O_B63;

    int tid = threadIdx.x;
    int bid = blockIdx.x;
    int h = bid & 31;
    int c = (bid >> 5) & 31;
    int b = bid >> 10;
    int blbase = b * SEQ + c * CH;

    for (int e = tid; e < CH*NK; e += CTH) {
        int t = e >> 5, k = e & 31;
        int bl = blbase + t;
        clr[t*KS+k] = g_lzr[(size_t)bl*(NH*NK) + h*NK + k];
        cli[t*KS+k] = g_lzi[(size_t)bl*(NH*NK) + h*NK + k];
        wre[t*KS+k] = g_Cr[bl*NK + k];
        wim[t*KS+k] = g_Ci[bl*NK + k];
        vr [t*KS+k] = g_Br[bl*NK + k];
        vi [t*KS+k] = g_Bi[bl*NK + k];
    }
    for (int e = tid; e < CH*HD; e += CTH) {
        int t = e >> 6, p = e & 63;
        int bl = blbase + t;
        xd[t*66+p] = g_xs[(size_t)bl*DIN + h*HD + p] * g_dt[bl*NH + h];
    }
    __syncthreads();

    if (tid < 32) {
        float sr = 0.f, si = 0.f;
        for (int t = 0; t < CH; t++) {
            sr += clr[t*KS+tid]; si += cli[t*KS+tid];
            clr[t*KS+tid] = sr;  cli[t*KS+tid] = si;
        }
    }
    __syncthreads();

    for (int e = tid; e < CH*NK; e += CTH) {
        int t = e >> 5, k = e & 31;
        float cs, sn; __sincosf(cli[t*KS+k], &sn, &cs);
        csT[t*KS+k] = cs; snT[t*KS+k] = sn;
        float er = __expf(clr[t*KS+k]);
        float exr = er*cs, exi = er*sn;
        float cr = wre[t*KS+k], ci = wim[t*KS+k];
        size_t base = (size_t)bid*(CH*NK) + t*NK + k;
        g_Pr[base] = cr*exr - ci*exi;
        g_Pi[base] = cr*exi + ci*exr;
        float br = vr[t*KS+k], bi = vi[t*KS+k];
        if (t == CH-1) {
            g_Er[bid*NK + k] = exr; g_Ei[bid*NK + k] = exi;
            b63[k] = br; b63[32+k] = bi;
        }
        float cbr = cr*br - ci*bi;
        float cbi = cr*bi + ci*br;
        int bs = t & ~15;
        float refI = (bs > 0) ? clr[(bs-1)*KS+k] : 0.f;
        float eu = __expf(clr[t*KS+k] - refI);
        float Ur = eu*cs, Ui = eu*sn;
        wre[t*KS+k] =  cbr*Ur - cbi*Ui;
        wim[t*KS+k] = -(cbr*Ui + cbi*Ur);
    }
    __syncthreads();

    int sp = tid & 31, tg = tid >> 5;   // tg 0..15
    for (int I = 0; I < 4; I++) {
        int tI0 = I << 4;
        for (int e = tid; e < NK*CH; e += CTH) {
            int k = e >> 6, s = e & 63;
            float vre = 0.f, vim_ = 0.f;
            if (s < tI0 + 16) {
                float refI = (I > 0) ? clr[(tI0-1)*KS+k] : 0.f;
                float ev = __expf(refI - clr[s*KS+k]);
                vre  =  ev * csT[s*KS+k];
                vim_ = -ev * snT[s*KS+k];
            }
            vr[k*66+s] = vre;
            vi[k*66+s] = vim_;
        }
        __syncthreads();

        {
            int tA = tI0 + tg;              // one t per warp-group of 32 lanes
            int s2 = sp << 1;
            ull accA = 0ULL;
            #pragma unroll 4
            for (int k = 0; k < NK; k++) {
                ull v_r = *(const ull*)&vr[k*66 + s2];
                ull v_i = *(const ull*)&vi[k*66 + s2];
                float wrA = wre[tA*KS+k], wiA = wim[tA*KS+k];
                FFMA2(accA, pack2(wrA, wrA), v_r);
                FFMA2(accA, pack2(wiA, wiA), v_i);
            }
            float2 aA = unpack2(accA);
            float2 gA = make_float2((s2   <= tA) ? aA.x : 0.f,
                                    (s2+1 <= tA) ? aA.y : 0.f);
            *(float2*)&G[tA*66 + s2] = gA;
        }
        __syncthreads();
    }

    float Dh = Dvec[h];
    for (int e = tid; e < CH*16; e += CTH) {
        int t = e >> 4, pq = (e & 15) << 2;
        ull a0 = 0ULL, a1 = 0ULL;
        for (int s = 0; s <= t; s++) {
            float gv = G[t*66+s];
            ull g2 = pack2(gv, gv);
            ull x0 = *(const ull*)&xd[s*66+pq];
            ull x1 = *(const ull*)&xd[s*66+pq+2];
            FFMA2(a0, g2, x0);
            FFMA2(a1, g2, x1);
        }
        float2 r0 = unpack2(a0), r1 = unpack2(a1);
        size_t yi = (size_t)(blbase + t)*DIN + h*HD + pq;
        float4 xv = *(const float4*)&g_xs[yi];
        float4 out4 = make_float4(r0.x + Dh*xv.x, r0.y + Dh*xv.y,
                                  r1.x + Dh*xv.z, r1.y + Dh*xv.w);
        *(float4*)&g_y[yi] = out4;
    }
    __syncthreads();

    for (int e = tid; e < CH*NK; e += CTH) {
        int s = e >> 5, k = e & 31;
        float er = __expf(clr[(CH-1)*KS+k] - clr[s*KS+k]);
        float c63 = csT[(CH-1)*KS+k], s63 = snT[(CH-1)*KS+k];
        float css = csT[s*KS+k],      sns = snT[s*KS+k];
        vr[s*KS+k] = er * (c63*css + s63*sns);
        vi[s*KS+k] = er * (s63*css - c63*sns);
    }
    __syncthreads();

    for (int e = tid; e < HD*16; e += CTH) {
        int p = e >> 4, k = (e & 15) << 1;
        ull ar = 0ULL, ai = 0ULL;
        for (int s = 0; s < CH; s++) {
            float xv = xd[s*66+p];
            ull x2 = pack2(xv, xv);
            ull v_r = *(const ull*)&vr[s*KS+k];
            ull v_i = *(const ull*)&vi[s*KS+k];
            FFMA2(ar, x2, v_r);
            FFMA2(ai, x2, v_i);
        }
        float2 arf = unpack2(ar), aif = unpack2(ai);
        float br0 = b63[k],   bi0 = b63[32+k];
        float br1 = b63[k+1], bi1 = b63[32+k+1];
        size_t di_ = (size_t)bid*(HD*NK) + p*NK + k;
        g_Dr[di_]   = br0*arf.x - bi0*aif.x;
        g_Di[di_]   = br0*aif.x + bi0*arf.x;
        g_Dr[di_+1] = br1*arf.y - bi1*aif.y;
        g_Di[di_+1] = br1*aif.y + bi1*arf.y;
    }
}

// ---------------- sequential scan over chunks (per b,h,p,k) ----------------------
__global__ void scan_kernel()
{
    int idx = blockIdx.x * blockDim.x + threadIdx.x;
    int k = idx & 31;
    int p = (idx >> 5) & 63;
    int h = (idx >> 11) & 31;
    int b = idx >> 16;
    float sr = 0.f, si = 0.f;
    for (int c = 0; c < NCH; c++) {
        int bidl = (b*NCH + c)*NH + h;
        size_t di_ = (size_t)bidl*(HD*NK) + p*NK + k;
        g_Sr[di_] = sr; g_Si[di_] = si;
        float er = g_Er[bidl*NK + k], ei = g_Ei[bidl*NK + k];
        float dr = g_Dr[di_], dimg = g_Di[di_];
        float nr = er*sr - ei*si + dr;
        float ni = er*si + ei*sr + dimg;
        sr = nr; si = ni;
    }
}

// ---------------- y += Re( P[t,k] * S_entry[p,k] )  (transposed S, packed) -------
__global__ __launch_bounds__(256) void yinter_kernel()
{
    __shared__ float Pr[CH*KS], Pi[CH*KS];
    __shared__ float SrT[NK*66], SiT[NK*66];
    int tid = threadIdx.x, bid = blockIdx.x;
    int h = bid & 31, c = (bid >> 5) & 31, b = bid >> 10;
    size_t base = (size_t)bid * (CH*NK);
    for (int e = tid; e < CH*NK; e += 256) {
        int t = e >> 5, k = e & 31;
        Pr[t*KS+k] =  g_Pr[base + e];
        Pi[t*KS+k] = -g_Pi[base + e];
        SrT[k*66+t] = g_Sr[base + e];
        SiT[k*66+t] = g_Si[base + e];
    }
    __syncthreads();
    int blbase = b*SEQ + c*CH;
    int sp = tid & 31, tg = tid >> 5;
    int p2 = sp << 1;
    #pragma unroll
    for (int it = 0; it < 4; it++) {
        int tA = 2*tg + 16*it, tB = tA + 1;
        ull aA = 0ULL, aB = 0ULL;
        #pragma unroll 4
        for (int k = 0; k < NK; k++) {
            ull s_r = *(const ull*)&SrT[k*66 + p2];
            ull s_i = *(const ull*)&SiT[k*66 + p2];
            float prA = Pr[tA*KS+k], piA = Pi[tA*KS+k];
            float prB = Pr[tB*KS+k], piB = Pi[tB*KS+k];
            FFMA2(aA, pack2(prA, prA), s_r);
            FFMA2(aA, pack2(piA, piA), s_i);
            FFMA2(aB, pack2(prB, prB), s_r);
            FFMA2(aB, pack2(piB, piB), s_i);
        }
        float2 fA = unpack2(aA), fB = unpack2(aB);
        size_t yA = (size_t)(blbase + tA)*DIN + h*HD + p2;
        size_t yB = (size_t)(blbase + tB)*DIN + h*HD + p2;
        float2 yvA = *(float2*)&g_y[yA];
        float2 yvB = *(float2*)&g_y[yB];
        yvA.x += fA.x; yvA.y += fA.y;
        yvB.x += fB.x; yvB.y += fB.y;
        *(float2*)&g_y[yA] = yvA;
        *(float2*)&g_y[yB] = yvB;
    }
}

// ---------------- gating + RMSNorm -> fp16 ---------------------------------------
__global__ __launch_bounds__(256) void gatenorm_kernel(const float* __restrict__ norm_w)
{
    __shared__ float red[8];
    int bl = blockIdx.x, tid = threadIdx.x;
    float gv[8];
    float local = 0.f;
    #pragma unroll
    for (int i = 0; i < 8; i++) {
        int j = tid + i*256;
        float z = g_zx[(size_t)bl*ZXSTR + j];
        float y = g_y[(size_t)bl*DIN + j];
        float sig = 1.f / (1.f + __expf(-z));
        float g = y * z * sig;
        gv[i] = g;
        local += g * g;
    }
    #pragma unroll
    for (int o = 16; o; o >>= 1) local += __shfl_xor_sync(0xffffffffu, local, o);
    if ((tid & 31) == 0) red[tid >> 5] = local;
    __syncthreads();
    if (tid == 0) {
        float s = 0.f;
        for (int i = 0; i < 8; i++) s += red[i];
        red[0] = rsqrtf(s / (float)DIN + 1e-5f);
    }
    __syncthreads();
    float sc = red[0];
    size_t ro = (size_t)bl * DIN;
    #pragma unroll
    for (int i = 0; i < 8; i++) {
        int j = tid + i*256;
        g_gh[ro + j] = __float2half(gv[i] * sc * norm_w[j]);
    }
}

// ---------------- launch ---------------------------------------------------------
extern "C" void kernel_launch(void* const* d_in, const int* in_sizes, int n_in,
                              void* d_out, int out_size)
{
    (void)in_sizes; (void)n_in; (void)out_size;
    const float* x       = (const float*)d_in[0];
    const float* in_w    = (const float*)d_in[1];
    const float* conv_w  = (const float*)d_in[2];
    const float* conv_b  = (const float*)d_in[3];
    const float* dt_bias = (const float*)d_in[4];
    const float* lam_b   = (const float*)d_in[5];
    const float* th_b    = (const float*)d_in[6];
    const float* w1      = (const float*)d_in[7];
    const float* w2      = (const float*)d_in[8];
    const float* eta     = (const float*)d_in[9];
    const float* Dv      = (const float*)d_in[10];
    const float* nw      = (const float*)d_in[11];
    const float* out_w   = (const float*)d_in[12];
    float* out = (float*)d_out;

    float *zx = nullptr;
    __half *xh, *wih, *gh, *woh;
    cudaGetSymbolAddress((void**)&zx,  g_zx);
    cudaGetSymbolAddress((void**)&xh,  g_xh);
    cudaGetSymbolAddress((void**)&wih, g_wih);
    cudaGetSymbolAddress((void**)&gh,  g_gh);
    cudaGetSymbolAddress((void**)&woh, g_woh);

    cudaFuncSetAttribute(gemm_half, cudaFuncAttributeMaxDynamicSharedMemorySize, GEMM_SMEM);
    cudaFuncSetAttribute(chunk_kernel, cudaFuncAttributeMaxDynamicSharedMemorySize, CHUNK_SMEM);

    // 0) converts
    tofp16_kernel<<<(BLTOT*DM/4+255)/256, 256>>>(x, xh, BLTOT*DM/4);
    tofp16_kernel<<<(DPROJ*DM/4+255)/256, 256>>>(in_w, wih, DPROJ*DM/4);
    splitW1_kernel<<<(DM*LR+255)/256, 256>>>(w1);
    tofp16_kernel<<<(DM*DIN/4+255)/256, 256>>>(out_w, woh, DM*DIN/4);

    // 1) in_proj (+fused lora1): 128x128 tiles (R12 config)
    gemm_half<<<dim3(NPAD_W/128, BLTOT/128), 256, GEMM_SMEM>>>(xh, wih, zx, BLTOT, ZXSTR, DM);
    // 2) conv (tiled) + silu + split + fused dt
    conv_kernel<<<dim3(9, BLTOT/8), 256>>>(conv_w, conv_b, dt_bias);
    // 3) lora stage 2 + log_z
    lora2_kernel<<<dim3(4, BLTOT/64), 256>>>(w2, th_b, lam_b, eta);
    // 4) chunk-parallel heavy kernel (512 threads)
    chunk_kernel<<<BATCHN*NCH*NH, CTH, CHUNK_SMEM>>>(Dv);
    // 5) inter-chunk state scan
    scan_kernel<<<(BATCHN*NH*HD*NK)/256, 256>>>();
    // 6) y += P * S_entry
    yinter_kernel<<<BATCHN*NCH*NH, 256>>>();
    // 7) gate + rmsnorm -> fp16
    gatenorm_kernel<<<BLTOT, 256>>>(nw);
    // 8) out_proj: 128x128 tiles
    gemm_half<<<dim3(DM/128, BLTOT/128), 256, GEMM_SMEM>>>(gh, woh, out, BLTOT, DM, DIN);
}

// round 17
// speedup vs baseline: 1.0531x; 1.0074x over previous
#include <cuda_runtime.h>
#include <cuda_fp16.h>
#include <math.h>

#define BATCHN 2
#define SEQ    2048
#define BLTOT  4096
#define DM     1024
#define DIN    2048
#define NH     32
#define HD     64
#define NK     32
#define CONVD  2176
#define DPROJ  4256
#define NCH    32
#define CH     64
#define LR     48
#define XBC_OFF 2048
#define DT_OFF  4224
#define T1_OFF  4256
#define ZXSTR   4352
#define THETA_CLIPF 1.5707963267948966f

#define NPAD_W 4352       // 34*128

typedef unsigned long long ull;

// ---------------- scratch (static device globals; no allocation) ----------------
__device__ __align__(256) float g_zx [BLTOT*ZXSTR];
__device__ __align__(256) float g_dt [BLTOT*NH];
__device__ __align__(256) float g_xs [BLTOT*DIN];
__device__ __align__(256) float g_Br [BLTOT*NK];
__device__ __align__(256) float g_Bi [BLTOT*NK];
__device__ __align__(256) float g_Cr [BLTOT*NK];
__device__ __align__(256) float g_Ci [BLTOT*NK];
__device__ __align__(256) float g_lzr[BLTOT*NH*NK];
__device__ __align__(256) float g_lzi[BLTOT*NH*NK];
__device__ __align__(256) float g_Pr [BATCHN*NCH*NH*CH*NK];
__device__ __align__(256) float g_Pi [BATCHN*NCH*NH*CH*NK];
__device__ __align__(256) float g_Er [BATCHN*NCH*NH*NK];
__device__ __align__(256) float g_Ei [BATCHN*NCH*NH*NK];
__device__ __align__(256) float g_Dr [BATCHN*NCH*NH*HD*NK];
__device__ __align__(256) float g_Di [BATCHN*NCH*NH*HD*NK];
__device__ __align__(256) float g_Sr [BATCHN*NCH*NH*HD*NK];
__device__ __align__(256) float g_Si [BATCHN*NCH*NH*HD*NK];
__device__ __align__(256) float g_y  [BLTOT*DIN];

// fp16 buffers (zero-initialized => pad rows are 0)
__device__ __align__(256) __half g_xh [BLTOT*DM];
__device__ __align__(256) __half g_wih[NPAD_W*DM];
__device__ __align__(256) __half g_gh [BLTOT*DIN];
__device__ __align__(256) __half g_woh[DM*DIN];

// ================= asm helpers ==================================================
#define LDSM4(R0,R1,R2,R3,ADDR) \
    asm volatile("ldmatrix.sync.aligned.m8n8.x4.shared.b16 {%0,%1,%2,%3}, [%4];" \
                 : "=r"(R0),"=r"(R1),"=r"(R2),"=r"(R3) : "r"(ADDR))

#define CP_ASYNC16(DST,SRC) \
    asm volatile("cp.async.cg.shared.global [%0], [%1], 16;" :: "r"(DST), "l"(SRC))
#define CP_COMMIT asm volatile("cp.async.commit_group;")
#define CP_WAITP  asm volatile("cp.async.wait_group 0;")

// packed f32x2 FMA: acc += a*b (elementwise)
#define FFMA2(ACC,A,B) \
    asm("fma.rn.f32x2 %0, %1, %2, %0;" : "+l"(ACC) : "l"(A), "l"(B))

__device__ __forceinline__ ull pack2(float x, float y)
{
    ull r; asm("mov.b64 %0, {%1, %2};" : "=l"(r) : "f"(x), "f"(y)); return r;
}
__device__ __forceinline__ float2 unpack2(ull v)
{
    float2 r; asm("mov.b64 {%0, %1}, %2;" : "=f"(r.x), "=f"(r.y) : "l"(v)); return r;
}

__device__ __forceinline__ unsigned smem_u32(const void* p)
{
    return (unsigned)__cvta_generic_to_shared(p);
}

__device__ __forceinline__ void mma_f16(float* d, const unsigned* a,
                                        unsigned b0, unsigned b1)
{
    asm volatile("mma.sync.aligned.m16n8k16.row.col.f32.f16.f16.f32 "
                 "{%0,%1,%2,%3}, {%4,%5,%6,%7}, {%8,%9}, {%0,%1,%2,%3};"
                 : "+f"(d[0]), "+f"(d[1]), "+f"(d[2]), "+f"(d[3])
                 : "r"(a[0]), "r"(a[1]), "r"(a[2]), "r"(a[3]), "r"(b0), "r"(b1));
}

// ================= fp16 GEMM: C[M,N] = A[M,K] * B[N,K]^T ========================
// 128x128 tile, BK=64, 2-stage cp.async double buffer, 2 CTAs/SM.  (R12 config)
#define GSTR 72
#define NSTG 2
#define STG_ELE (128*GSTR)
#define GEMM_SMEM (NSTG * 2 * STG_ELE * 2)  // 73728 bytes

__global__ __launch_bounds__(256, 2) void gemm_half(const __half* __restrict__ A,
                                                    const __half* __restrict__ B,
                                                    float* __restrict__ C,
                                                    int M, int N, int K)
{
    extern __shared__ __align__(16) __half smg[];
    __half* sA = smg;
    __half* sB = smg + NSTG*STG_ELE;

    int tid = threadIdx.x, lane = tid & 31, wid = tid >> 5;
    int wm = wid & 3;
    int wn = wid >> 2;
    int row0 = blockIdx.y * 128, col0 = blockIdx.x * 128;

    float acc[2][8][4];
    #pragma unroll
    for (int a = 0; a < 2; a++)
        #pragma unroll
        for (int b = 0; b < 8; b++)
            #pragma unroll
            for (int c = 0; c < 4; c++) acc[a][b][c] = 0.f;

    int NT = K >> 6;

    {
        #pragma unroll
        for (int i = 0; i < 4; i++) {
            int f = tid + i*256, r = f >> 3, kc = (f & 7) << 3;
            CP_ASYNC16(smem_u32(&sA[r*GSTR + kc]), A + (size_t)(row0+r)*K + kc);
            CP_ASYNC16(smem_u32(&sB[r*GSTR + kc]), B + (size_t)(col0+r)*K + kc);
        }
        CP_COMMIT;
    }

    for (int kt = 0; kt < NT; kt++) {
        CP_WAITP;
        __syncthreads();

        {
            int kf = kt + 1;
            if (kf < NT) {
                int s = kf & 1, k0 = kf << 6;
                #pragma unroll
                for (int i = 0; i < 4; i++) {
                    int f = tid + i*256, r = f >> 3, kc = (f & 7) << 3;
                    CP_ASYNC16(smem_u32(&sA[s*STG_ELE + r*GSTR + kc]), A + (size_t)(row0+r)*K + k0 + kc);
                    CP_ASYNC16(smem_u32(&sB[s*STG_ELE + r*GSTR + kc]), B + (size_t)(col0+r)*K + k0 + kc);
                }
                CP_COMMIT;
            }
        }

        const __half* a_s = sA + (kt & 1)*STG_ELE;
        const __half* b_s = sB + (kt & 1)*STG_ELE;

        #pragma unroll
        for (int kh = 0; kh < 64; kh += 16) {
            unsigned ah[2][4];
            #pragma unroll
            for (int mf = 0; mf < 2; mf++) {
                int r = wm*32 + mf*16 + (lane & 15);
                int cc = kh + ((lane >> 4) << 3);
                LDSM4(ah[mf][0], ah[mf][1], ah[mf][2], ah[mf][3],
                      smem_u32(&a_s[r*GSTR + cc]));
            }
            #pragma unroll
            for (int np = 0; np < 4; np++) {
                int nr  = wn*64 + np*16 + (lane & 7) + ((lane >> 4) << 3);
                int kof = kh + (((lane >> 3) & 1) << 3);
                unsigned bh[4];
                LDSM4(bh[0], bh[1], bh[2], bh[3], smem_u32(&b_s[nr*GSTR + kof]));
                #pragma unroll
                for (int mf = 0; mf < 2; mf++) {
                    mma_f16(acc[mf][np*2+0], ah[mf], bh[0], bh[1]);
                    mma_f16(acc[mf][np*2+1], ah[mf], bh[2], bh[3]);
                }
            }
        }
    }

    #pragma unroll
    for (int mf = 0; mf < 2; mf++) {
        int r = row0 + wm*32 + mf*16 + (lane >> 2);
        #pragma unroll
        for (int nf = 0; nf < 8; nf++) {
            int c = col0 + wn*64 + nf*8 + ((lane & 3) << 1);
            if (c + 1 < N) {
                *(float2*)&C[(size_t)r*N + c]     = make_float2(acc[mf][nf][0], acc[mf][nf][1]);
                *(float2*)&C[(size_t)(r+8)*N + c] = make_float2(acc[mf][nf][2], acc[mf][nf][3]);
            } else if (c < N) {
                C[(size_t)r*N + c]     = acc[mf][nf][0];
                C[(size_t)(r+8)*N + c] = acc[mf][nf][2];
            }
        }
    }
}

// ---------------- plain fp32 -> fp16 convert ------------------------------------
__global__ void tofp16_kernel(const float* __restrict__ src,
                              __half* __restrict__ dst, int n4)
{
    int i = blockIdx.x * blockDim.x + threadIdx.x;
    if (i >= n4) return;
    float4 v = *(const float4*)(src + i*4);
    __half2 a, b;
    a.x = __float2half(v.x); a.y = __float2half(v.y);
    b.x = __float2half(v.z); b.y = __float2half(v.w);
    ((__half2*)(dst + i*4))[0] = a;
    ((__half2*)(dst + i*4))[1] = b;
}

// ---------------- w1 (DM x LR) -> rows T1_OFF.. of g_wih ------------------------
__global__ void splitW1_kernel(const float* __restrict__ w1)
{
    int idx = blockIdx.x * blockDim.x + threadIdx.x;
    if (idx >= DM * LR) return;
    int k = idx / LR, n = idx % LR;
    g_wih[(size_t)(T1_OFF + n) * DM + k] = __float2half(w1[idx]);
}

// ---------------- depthwise causal conv (smem-tiled) + silu + split + dt ---------
// channels [0, CONVD): conv.  channels [CONVD, CONVD+NH): dt = softplus(...).
// Note XBC_OFF + CONVD == DT_OFF, so the tile already holds the dt inputs.
__global__ __launch_bounds__(256) void conv_kernel(const float* __restrict__ conv_w,
                                                   const float* __restrict__ conv_b,
                                                   const float* __restrict__ dt_bias)
{
    __shared__ float tile[11][256];
    int tid = threadIdx.x;
    int c0 = blockIdx.x * 256;
    int bl0 = blockIdx.y * 8;
    int lblk = bl0 & (SEQ - 1);

    int c = c0 + tid;
    #pragma unroll
    for (int r = 0; r < 11; r++) {
        float v = 0.f;
        int off = r - 3;
        if (c < CONVD + NH && lblk + off >= 0)
            v = g_zx[(size_t)(bl0 + off) * ZXSTR + XBC_OFF + c];
        tile[r][tid] = v;
    }
    __syncthreads();

    if (c >= CONVD + NH) return;

    if (c >= CONVD) {
        int hh = c - CONVD;
        float bsv = dt_bias[hh];
        #pragma unroll
        for (int r = 0; r < 8; r++) {
            float v = tile[r+3][tid] + bsv;
            float sp = (v > 20.f) ? v : log1pf(expf(v));
            g_dt[(bl0 + r)*NH + hh] = sp;
        }
        return;
    }

    float w0 = conv_w[c*4+0], w1 = conv_w[c*4+1], w2 = conv_w[c*4+2], w3 = conv_w[c*4+3];
    float bias = conv_b[c];

    #pragma unroll
    for (int r = 0; r < 8; r++) {
        float acc = bias + tile[r][tid]*w0 + tile[r+1][tid]*w1
                         + tile[r+2][tid]*w2 + tile[r+3][tid]*w3;
        float a = acc / (1.f + __expf(-acc));
        int bl = bl0 + r;
        if (c < DIN) {
            g_xs[(size_t)bl * DIN + c] = a;
        } else {
            int c2 = c - DIN;
            if (c2 < 64) {
                int k = c2 >> 1;
                if (c2 & 1) g_Bi[bl*NK + k] = a; else g_Br[bl*NK + k] = a;
            } else {
                int c3 = c2 - 64;
                int k = c3 >> 1;
                if (c3 & 1) g_Ci[bl*NK + k] = a; else g_Cr[bl*NK + k] = a;
            }
        }
    }
}

// ---------------- lora2 (tanh applied on load, t1 from zx columns) ---------------
__global__ __launch_bounds__(256) void lora2_kernel(const float* __restrict__ w2,
                                                    const float* __restrict__ theta_base,
                                                    const float* __restrict__ lambda_base,
                                                    const float* __restrict__ eta)
{
    __shared__ float t1s[64][LR];
    __shared__ float w2s[LR][256];
    int tid = threadIdx.x;
    int row0 = blockIdx.y * 64;
    int col0 = blockIdx.x * 256;
    int n = col0 + tid;

    for (int idx = tid; idx < 64*LR; idx += 256) {
        int r = idx / LR, j = idx % LR;
        t1s[r][j] = tanhf(g_zx[(size_t)(row0 + r)*ZXSTR + T1_OFF + j]);
    }
    for (int idx = tid; idx < LR*256; idx += 256) {
        int j = idx >> 8, cc = idx & 255;
        w2s[j][cc] = w2[(size_t)j*(NH*NK) + col0 + cc];
    }
    __syncthreads();

    float tb = theta_base[n];
    float lb = lambda_base[n];
    float et = eta[n];
    int hh = n >> 5;

    for (int r = 0; r < 64; r++) {
        float acc = 0.f;
        #pragma unroll
        for (int j = 0; j < LR; j++) acc += t1s[r][j] * w2s[j][tid];
        float th = tb + acc;
        th = fminf(fmaxf(th, -THETA_CLIPF), THETA_CLIPF);
        float lam = lb + et * th * th;
        int bl = row0 + r;
        float dtv = g_dt[bl*NH + hh];
        g_lzr[(size_t)bl*(NH*NK) + n] = -lam * dtv;
        g_lzi[(size_t)bl*(NH*NK) + n] =  th * dtv;
    }
}

// ---------------- per-chunk kernel (factorized, 512 threads) ---------------------
#define KS 34
#define O_CLR 0
#define O_CLI (1*64*KS)
#define O_CST (2*64*KS)
#define O_SNT (3*64*KS)
#define O_WRE (4*64*KS)
#define O_WIM (5*64*KS)
#define O_VR  (6*64*KS)
#define O_VI  (7*64*KS)
#define O_XD  (8*64*KS)            // 64x66
#define O_G   (8*64*KS + 64*66)    // 64x66
#define O_B63 (8*64*KS + 2*64*66)
#define CHUNK_FLOATS (O_B63 + 64)
#define CHUNK_SMEM (CHUNK_FLOATS*4)
#define CTH 512

__global__ __launch_bounds__(CTH) void chunk_kernel(const float* __restrict__ Dvec)
{
    extern __shared__ float sm[];
    float* clr = sm + O_CLR;
    float* cli = sm + O_CLI;
    float* csT = sm + O_CST;
    float* snT = sm + O_SNT;
    float* wre = sm + O_WRE;
    float* wim = sm + O_WIM;
    float* vr  = sm + O_VR;
    float* vi  = sm + O_VI;
    float* xd  = sm + O_XD;
    float* G   = sm + O_G;
    float* b63 = sm + O_B63;

    int tid = threadIdx.x;
    int bid = blockIdx.x;
    int h = bid & 31;
    int c = (bid >> 5) & 31;
    int b = bid >> 10;
    int blbase = b * SEQ + c * CH;

    for (int e = tid; e < CH*NK; e += CTH) {
        int t = e >> 5, k = e & 31;
        int bl = blbase + t;
        clr[t*KS+k] = g_lzr[(size_t)bl*(NH*NK) + h*NK + k];
        cli[t*KS+k] = g_lzi[(size_t)bl*(NH*NK) + h*NK + k];
        wre[t*KS+k] = g_Cr[bl*NK + k];
        wim[t*KS+k] = g_Ci[bl*NK + k];
        vr [t*KS+k] = g_Br[bl*NK + k];
        vi [t*KS+k] = g_Bi[bl*NK + k];
    }
    for (int e = tid; e < CH*HD; e += CTH) {
        int t = e >> 6, p = e & 63;
        int bl = blbase + t;
        xd[t*66+p] = g_xs[(size_t)bl*DIN + h*HD + p] * g_dt[bl*NH + h];
    }
    __syncthreads();

    if (tid < 32) {
        float sr = 0.f, si = 0.f;
        for (int t = 0; t < CH; t++) {
            sr += clr[t*KS+tid]; si += cli[t*KS+tid];
            clr[t*KS+tid] = sr;  cli[t*KS+tid] = si;
        }
    }
    __syncthreads();

    for (int e = tid; e < CH*NK; e += CTH) {
        int t = e >> 5, k = e & 31;
        float cs, sn; __sincosf(cli[t*KS+k], &sn, &cs);
        csT[t*KS+k] = cs; snT[t*KS+k] = sn;
        float er = __expf(clr[t*KS+k]);
        float exr = er*cs, exi = er*sn;
        float cr = wre[t*KS+k], ci = wim[t*KS+k];
        size_t base = (size_t)bid*(CH*NK) + t*NK + k;
        g_Pr[base] = cr*exr - ci*exi;
        g_Pi[base] = cr*exi + ci*exr;
        float br = vr[t*KS+k], bi = vi[t*KS+k];
        if (t == CH-1) {
            g_Er[bid*NK + k] = exr; g_Ei[bid*NK + k] = exi;
            b63[k] = br; b63[32+k] = bi;
        }
        float cbr = cr*br - ci*bi;
        float cbi = cr*bi + ci*br;
        int bs = t & ~15;
        float refI = (bs > 0) ? clr[(bs-1)*KS+k] : 0.f;
        float eu = __expf(clr[t*KS+k] - refI);
        float Ur = eu*cs, Ui = eu*sn;
        wre[t*KS+k] =  cbr*Ur - cbi*Ui;
        wim[t*KS+k] = -(cbr*Ui + cbi*Ur);
    }
    __syncthreads();

    int sp = tid & 31, tg = tid >> 5;   // tg 0..15
    for (int I = 0; I < 4; I++) {
        int tI0 = I << 4;
        for (int e = tid; e < NK*CH; e += CTH) {
            int k = e >> 6, s = e & 63;
            float vre = 0.f, vim_ = 0.f;
            if (s < tI0 + 16) {
                float refI = (I > 0) ? clr[(tI0-1)*KS+k] : 0.f;
                float ev = __expf(refI - clr[s*KS+k]);
                vre  =  ev * csT[s*KS+k];
                vim_ = -ev * snT[s*KS+k];
            }
            vr[k*66+s] = vre;
            vi[k*66+s] = vim_;
        }
        __syncthreads();

        {
            int tA = tI0 + tg;              // one t per warp-group of 32 lanes
            int s2 = sp << 1;
            ull accA = 0ULL;
            #pragma unroll 4
            for (int k = 0; k < NK; k++) {
                ull v_r = *(const ull*)&vr[k*66 + s2];
                ull v_i = *(const ull*)&vi[k*66 + s2];
                float wrA = wre[tA*KS+k], wiA = wim[tA*KS+k];
                FFMA2(accA, pack2(wrA, wrA), v_r);
                FFMA2(accA, pack2(wiA, wiA), v_i);
            }
            float2 aA = unpack2(accA);
            float2 gA = make_float2((s2   <= tA) ? aA.x : 0.f,
                                    (s2+1 <= tA) ? aA.y : 0.f);
            *(float2*)&G[tA*66 + s2] = gA;
        }
        __syncthreads();
    }

    float Dh = Dvec[h];
    for (int e = tid; e < CH*16; e += CTH) {
        int t = e >> 4, pq = (e & 15) << 2;
        ull a0 = 0ULL, a1 = 0ULL;
        for (int s = 0; s <= t; s++) {
            float gv = G[t*66+s];
            ull g2 = pack2(gv, gv);
            ull x0 = *(const ull*)&xd[s*66+pq];
            ull x1 = *(const ull*)&xd[s*66+pq+2];
            FFMA2(a0, g2, x0);
            FFMA2(a1, g2, x1);
        }
        float2 r0 = unpack2(a0), r1 = unpack2(a1);
        size_t yi = (size_t)(blbase + t)*DIN + h*HD + pq;
        float4 xv = *(const float4*)&g_xs[yi];
        float4 out4 = make_float4(r0.x + Dh*xv.x, r0.y + Dh*xv.y,
                                  r1.x + Dh*xv.z, r1.y + Dh*xv.w);
        *(float4*)&g_y[yi] = out4;
    }
    __syncthreads();

    for (int e = tid; e < CH*NK; e += CTH) {
        int s = e >> 5, k = e & 31;
        float er = __expf(clr[(CH-1)*KS+k] - clr[s*KS+k]);
        float c63 = csT[(CH-1)*KS+k], s63 = snT[(CH-1)*KS+k];
        float css = csT[s*KS+k],      sns = snT[s*KS+k];
        vr[s*KS+k] = er * (c63*css + s63*sns);
        vi[s*KS+k] = er * (s63*css - c63*sns);
    }
    __syncthreads();

    for (int e = tid; e < HD*16; e += CTH) {
        int p = e >> 4, k = (e & 15) << 1;
        ull ar = 0ULL, ai = 0ULL;
        for (int s = 0; s < CH; s++) {
            float xv = xd[s*66+p];
            ull x2 = pack2(xv, xv);
            ull v_r = *(const ull*)&vr[s*KS+k];
            ull v_i = *(const ull*)&vi[s*KS+k];
            FFMA2(ar, x2, v_r);
            FFMA2(ai, x2, v_i);
        }
        float2 arf = unpack2(ar), aif = unpack2(ai);
        float br0 = b63[k],   bi0 = b63[32+k];
        float br1 = b63[k+1], bi1 = b63[32+k+1];
        size_t di_ = (size_t)bid*(HD*NK) + p*NK + k;
        g_Dr[di_]   = br0*arf.x - bi0*aif.x;
        g_Di[di_]   = br0*aif.x + bi0*arf.x;
        g_Dr[di_+1] = br1*arf.y - bi1*aif.y;
        g_Di[di_+1] = br1*aif.y + bi1*arf.y;
    }
}

// ---------------- sequential scan over chunks (per b,h,p,k) ----------------------
__global__ void scan_kernel()
{
    int idx = blockIdx.x * blockDim.x + threadIdx.x;
    int k = idx & 31;
    int p = (idx >> 5) & 63;
    int h = (idx >> 11) & 31;
    int b = idx >> 16;
    float sr = 0.f, si = 0.f;
    for (int c = 0; c < NCH; c++) {
        int bidl = (b*NCH + c)*NH + h;
        size_t di_ = (size_t)bidl*(HD*NK) + p*NK + k;
        g_Sr[di_] = sr; g_Si[di_] = si;
        float er = g_Er[bidl*NK + k], ei = g_Ei[bidl*NK + k];
        float dr = g_Dr[di_], dimg = g_Di[di_];
        float nr = er*sr - ei*si + dr;
        float ni = er*si + ei*sr + dimg;
        sr = nr; si = ni;
    }
}

// ---------------- y += Re( P[t,k] * S_entry[p,k] )  (transposed S, packed) -------
__global__ __launch_bounds__(256) void yinter_kernel()
{
    __shared__ float Pr[CH*KS], Pi[CH*KS];
    __shared__ float SrT[NK*66], SiT[NK*66];
    int tid = threadIdx.x, bid = blockIdx.x;
    int h = bid & 31, c = (bid >> 5) & 31, b = bid >> 10;
    size_t base = (size_t)bid * (CH*NK);
    for (int e = tid; e < CH*NK; e += 256) {
        int t = e >> 5, k = e & 31;
        Pr[t*KS+k] =  g_Pr[base + e];
        Pi[t*KS+k] = -g_Pi[base + e];
        SrT[k*66+t] = g_Sr[base + e];
        SiT[k*66+t] = g_Si[base + e];
    }
    __syncthreads();
    int blbase = b*SEQ + c*CH;
    int sp = tid & 31, tg = tid >> 5;
    int p2 = sp << 1;
    #pragma unroll
    for (int it = 0; it < 4; it++) {
        int tA = 2*tg + 16*it, tB = tA + 1;
        ull aA = 0ULL, aB = 0ULL;
        #pragma unroll 4
        for (int k = 0; k < NK; k++) {
            ull s_r = *(const ull*)&SrT[k*66 + p2];
            ull s_i = *(const ull*)&SiT[k*66 + p2];
            float prA = Pr[tA*KS+k], piA = Pi[tA*KS+k];
            float prB = Pr[tB*KS+k], piB = Pi[tB*KS+k];
            FFMA2(aA, pack2(prA, prA), s_r);
            FFMA2(aA, pack2(piA, piA), s_i);
            FFMA2(aB, pack2(prB, prB), s_r);
            FFMA2(aB, pack2(piB, piB), s_i);
        }
        float2 fA = unpack2(aA), fB = unpack2(aB);
        size_t yA = (size_t)(blbase + tA)*DIN + h*HD + p2;
        size_t yB = (size_t)(blbase + tB)*DIN + h*HD + p2;
        float2 yvA = *(float2*)&g_y[yA];
        float2 yvB = *(float2*)&g_y[yB];
        yvA.x += fA.x; yvA.y += fA.y;
        yvB.x += fB.x; yvB.y += fB.y;
        *(float2*)&g_y[yA] = yvA;
        *(float2*)&g_y[yB] = yvB;
    }
}

// ---------------- gating + RMSNorm -> fp16 ---------------------------------------
__global__ __launch_bounds__(256) void gatenorm_kernel(const float* __restrict__ norm_w)
{
    __shared__ float red[8];
    int bl = blockIdx.x, tid = threadIdx.x;
    float gv[8];
    float local = 0.f;
    #pragma unroll
    for (int i = 0; i < 8; i++) {
        int j = tid + i*256;
        float z = g_zx[(size_t)bl*ZXSTR + j];
        float y = g_y[(size_t)bl*DIN + j];
        float sig = 1.f / (1.f + __expf(-z));
        float g = y * z * sig;
        gv[i] = g;
        local += g * g;
    }
    #pragma unroll
    for (int o = 16; o; o >>= 1) local += __shfl_xor_sync(0xffffffffu, local, o);
    if ((tid & 31) == 0) red[tid >> 5] = local;
    __syncthreads();
    if (tid == 0) {
        float s = 0.f;
        for (int i = 0; i < 8; i++) s += red[i];
        red[0] = rsqrtf(s / (float)DIN + 1e-5f);
    }
    __syncthreads();
    float sc = red[0];
    size_t ro = (size_t)bl * DIN;
    #pragma unroll
    for (int i = 0; i < 8; i++) {
        int j = tid + i*256;
        g_gh[ro + j] = __float2half(gv[i] * sc * norm_w[j]);
    }
}

// ---------------- launch ---------------------------------------------------------
extern "C" void kernel_launch(void* const* d_in, const int* in_sizes, int n_in,
                              void* d_out, int out_size)
{
    (void)in_sizes; (void)n_in; (void)out_size;
    const float* x       = (const float*)d_in[0];
    const float* in_w    = (const float*)d_in[1];
    const float* conv_w  = (const float*)d_in[2];
    const float* conv_b  = (const float*)d_in[3];
    const float* dt_bias = (const float*)d_in[4];
    const float* lam_b   = (const float*)d_in[5];
    const float* th_b    = (const float*)d_in[6];
    const float* w1      = (const float*)d_in[7];
    const float* w2      = (const float*)d_in[8];
    const float* eta     = (const float*)d_in[9];
    const float* Dv      = (const float*)d_in[10];
    const float* nw      = (const float*)d_in[11];
    const float* out_w   = (const float*)d_in[12];
    float* out = (float*)d_out;

    float *zx = nullptr;
    __half *xh, *wih, *gh, *woh;
    cudaGetSymbolAddress((void**)&zx,  g_zx);
    cudaGetSymbolAddress((void**)&xh,  g_xh);
    cudaGetSymbolAddress((void**)&wih, g_wih);
    cudaGetSymbolAddress((void**)&gh,  g_gh);
    cudaGetSymbolAddress((void**)&woh, g_woh);

    cudaFuncSetAttribute(gemm_half, cudaFuncAttributeMaxDynamicSharedMemorySize, GEMM_SMEM);
    cudaFuncSetAttribute(chunk_kernel, cudaFuncAttributeMaxDynamicSharedMemorySize, CHUNK_SMEM);

    // 0) converts
    tofp16_kernel<<<(BLTOT*DM/4+255)/256, 256>>>(x, xh, BLTOT*DM/4);
    tofp16_kernel<<<(DPROJ*DM/4+255)/256, 256>>>(in_w, wih, DPROJ*DM/4);
    splitW1_kernel<<<(DM*LR+255)/256, 256>>>(w1);
    tofp16_kernel<<<(DM*DIN/4+255)/256, 256>>>(out_w, woh, DM*DIN/4);

    // 1) in_proj (+fused lora1): 128x128 tiles (R12 config)
    gemm_half<<<dim3(NPAD_W/128, BLTOT/128), 256, GEMM_SMEM>>>(xh, wih, zx, BLTOT, ZXSTR, DM);
    // 2) conv (tiled) + silu + split + fused dt
    conv_kernel<<<dim3(9, BLTOT/8), 256>>>(conv_w, conv_b, dt_bias);
    // 3) lora stage 2 + log_z
    lora2_kernel<<<dim3(4, BLTOT/64), 256>>>(w2, th_b, lam_b, eta);
    // 4) chunk-parallel heavy kernel (512 threads)
    chunk_kernel<<<BATCHN*NCH*NH, CTH, CHUNK_SMEM>>>(Dv);
    // 5) inter-chunk state scan
    scan_kernel<<<(BATCHN*NH*HD*NK)/256, 256>>>();
    // 6) y += P * S_entry
    yinter_kernel<<<BATCHN*NCH*NH, 256>>>();
    // 7) gate + rmsnorm -> fp16
    gatenorm_kernel<<<BLTOT, 256>>>(nw);
    // 8) out_proj: 128x128 tiles
    gemm_half<<<dim3(DM/128, BLTOT/128), 256, GEMM_SMEM>>>(gh, woh, out, BLTOT, DM, DIN);
}